// round 12
// baseline (speedup 1.0000x reference)
#include <cuda_runtime.h>

#define BB    8
#define DD    472
#define CC    472
#define FHH   56
#define FWW   100
#define NPIX  (FHH * FWW)      // 5600
#define NXX   160
#define NYY   160

#define SEGS       8
#define BINS_SEG   59                        // 8 * 59 = 472
#define ARG_BLOCKS  ((BB * NPIX) / 32)       // 1400
#define ZERO_BLOCKS 8072
#define SCAT_BLOCKS ((BB * NPIX) / 8)        // 5600 (warp per pixel, 8 warps/block)
#define TOTAL_BLOCKS (ARG_BLOCKS + ZERO_BLOCKS + SCAT_BLOCKS)
#define NCHUNK     (CC / 4)                  // 118 float4 chunks

// per-pixel BEV segment (or -1), rewritten fully every launch
__device__ int pix2seg_g[BB * NPIX];
// progress counters (zero at load; self-reset by last scatter block each launch)
__device__ unsigned arg_done_g;
__device__ unsigned zero_done_g;
__device__ unsigned scat_done_g;

__device__ __forceinline__ void inv3x3(const float a[9], float m[9]) {
    float A  =  (a[4] * a[8] - a[5] * a[7]);
    float Bc = -(a[3] * a[8] - a[5] * a[6]);
    float Cc =  (a[3] * a[7] - a[4] * a[6]);
    float Dv = -(a[1] * a[8] - a[2] * a[7]);
    float E  =  (a[0] * a[8] - a[2] * a[6]);
    float F  = -(a[0] * a[7] - a[1] * a[6]);
    float G  =  (a[1] * a[5] - a[2] * a[4]);
    float Hc = -(a[0] * a[5] - a[2] * a[3]);
    float I  =  (a[0] * a[4] - a[1] * a[3]);
    float det = a[0] * A + a[1] * Bc + a[2] * Cc;
    m[0] = A  / det;  m[1] = Dv / det;  m[2] = G  / det;
    m[3] = Bc / det;  m[4] = E  / det;  m[5] = Hc / det;
    m[6] = Cc / det;  m[7] = F  / det;  m[8] = I  / det;
}

__device__ __forceinline__ void red_add_v4(float* addr, float a, float b,
                                           float c, float d) {
    asm volatile("red.global.add.v4.f32 [%0], {%1, %2, %3, %4};"
                 :: "l"(addr), "f"(a), "f"(b), "f"(c), "f"(d) : "memory");
}

__global__ void __launch_bounds__(256)
mega_kernel(const float* __restrict__ depth,   // [B, D, FH, FW]
            const float* __restrict__ feats,   // [B, C, FH, FW]
            const float* __restrict__ intr,    // [B, 3, 3]
            const float* __restrict__ rot,     // [B, 3, 3]
            float* __restrict__ out,           // [B, NX, NY, C]
            long long nout)
{
    int bx  = blockIdx.x;
    int tid = threadIdx.x;

    // ===================== role 2: zero-fill =====================
    if (bx >= ARG_BLOCKS && bx < ARG_BLOCKS + ZERO_BLOCKS) {
        long long n4 = nout >> 2;
        float4* o4 = reinterpret_cast<float4*>(out);
        long long i = (long long)(bx - ARG_BLOCKS) * 256 + tid;
        long long stride = (long long)ZERO_BLOCKS * 256;
        float4 z = make_float4(0.f, 0.f, 0.f, 0.f);
        for (; i < n4; i += stride) __stcs(&o4[i], z);
        __syncthreads();
        if (tid == 0) { __threadfence(); atomicAdd(&zero_done_g, 1u); }
        return;
    }

    // ===================== role 3: scatter =====================
    if (bx >= ARG_BLOCKS + ZERO_BLOCKS) {
        int sb   = bx - (ARG_BLOCKS + ZERO_BLOCKS);
        int lane = tid & 31;
        int wid  = tid >> 5;
        int pix  = sb * 8 + wid;                 // warp per pixel

        // gate1: pix2seg ready (arg blocks are waves earlier; usually instant)
        if (tid == 0) {
            while (atomicAdd(&arg_done_g, 0u) < ARG_BLOCKS) __nanosleep(64);
            __threadfence();
        }
        __syncthreads();

        int seg = __ldg(&pix2seg_g[pix]);

        int b  = pix / NPIX;
        int hw = pix - b * NPIX;
        const float* fp = feats + (size_t)b * CC * NPIX + hw;

        float v[4][4];
        bool has4 = (lane < (NCHUNK - 96));      // lane < 22
        if (seg >= 0) {
            #pragma unroll
            for (int r = 0; r < 3; r++) {
                int c = (r * 32 + lane) * 4;
                #pragma unroll
                for (int k = 0; k < 4; k++)
                    v[r][k] = __ldg(&fp[(size_t)(c + k) * NPIX]);
            }
            if (has4) {
                int c = (96 + lane) * 4;
                #pragma unroll
                for (int k = 0; k < 4; k++)
                    v[3][k] = __ldg(&fp[(size_t)(c + k) * NPIX]);
            }
        }

        // gate2: output fully zeroed
        if (tid == 0) {
            while (atomicAdd(&zero_done_g, 0u) < ZERO_BLOCKS) __nanosleep(64);
            __threadfence();
        }
        __syncthreads();

        if (seg >= 0) {
            float* op = out + (size_t)seg * CC;
            #pragma unroll
            for (int r = 0; r < 3; r++) {
                int c = (r * 32 + lane) * 4;
                red_add_v4(&op[c], v[r][0], v[r][1], v[r][2], v[r][3]);
            }
            if (has4) {
                int c = (96 + lane) * 4;
                red_add_v4(&op[c], v[3][0], v[3][1], v[3][2], v[3][3]);
            }
        }

        __syncthreads();
        if (tid == 0) {
            unsigned d = atomicAdd(&scat_done_g, 1u) + 1u;
            if (d == SCAT_BLOCKS) {       // last scatter block: reset for replay
                arg_done_g  = 0u;
                zero_done_g = 0u;
                scat_done_g = 0u;
                __threadfence();
            }
        }
        return;
    }

    // ===================== role 1: argmax + geometry =====================
    int tx = tid & 31;            // pixel within tile
    int ty = tid >> 5;            // depth segment
    int pix = bx * 32 + tx;
    int b  = pix / NPIX;
    int hw = pix - b * NPIX;

    const float* dp = depth + (size_t)b * DD * NPIX + hw;
    int base = ty * BINS_SEG;
    float best = dp[(size_t)base * NPIX];
    int   bi   = base;
    #pragma unroll
    for (int k = 1; k < BINS_SEG; k++) {
        float vv = dp[(size_t)(base + k) * NPIX];
        if (vv > best) { best = vv; bi = base + k; }
    }

    __shared__ float sval[SEGS][32];
    __shared__ int   sidx[SEGS][32];
    sval[ty][tx] = best;
    sidx[ty][tx] = bi;
    __syncthreads();

    if (ty == 0) {
        // reduce across depth segments in ascending order (first max wins)
        float bv = sval[0][tx];
        int  bix = sidx[0][tx];
        #pragma unroll
        for (int s = 1; s < SEGS; s++) {
            float vv = sval[s][tx];
            if (vv > bv) { bv = vv; bix = sidx[s][tx]; }
        }
        float d = (float)bix * 0.125f + 1.0f;

        // combine = R * inv(K), float32, ascending-j fma
        float a[9], invK[9], Cm[9];
        #pragma unroll
        for (int i = 0; i < 9; i++) a[i] = intr[b * 9 + i];
        inv3x3(a, invK);
        #pragma unroll
        for (int i = 0; i < 3; i++) {
            #pragma unroll
            for (int j = 0; j < 3; j++) {
                float acc = rot[b * 9 + i * 3 + 0] * invK[0 * 3 + j];
                acc = fmaf(rot[b * 9 + i * 3 + 1], invK[1 * 3 + j], acc);
                acc = fmaf(rot[b * 9 + i * 3 + 2], invK[2 * 3 + j], acc);
                Cm[i * 3 + j] = acc;
            }
        }

        int h = hw / FWW;
        int w = hw - h * FWW;
        const float DU = 1600.0f / 99.0f;
        const float DV = 896.0f / 55.0f;
        float u  = (float)w * DU;
        float v  = (float)h * DV;
        float ud = u * d;
        float vd = v * d;

        float x = fmaf(Cm[2], d, fmaf(Cm[1], vd, Cm[0] * ud));
        float y = fmaf(Cm[5], d, fmaf(Cm[4], vd, Cm[3] * ud));
        float z = fmaf(Cm[8], d, fmaf(Cm[7], vd, Cm[6] * ud));

        bool inb = (x > 1.0f) && (x < 41.0f) &&
                   (y > -20.0f) && (y < 20.0f) &&
                   (z > -10.0f) && (z < 10.0f);
        float fxv = floorf((x - 1.0f) * 4.0f);
        float fyv = floorf((y + 20.0f) * 4.0f);
        float fzv = floorf((z + 10.0f) / 20.0f);
        int xi = (int)fxv, yi = (int)fyv, zi = (int)fzv;
        bool ing = (xi >= 0) && (xi < NXX) && (yi >= 0) && (yi < NYY) &&
                   (zi >= 0) && (zi < 1);

        pix2seg_g[pix] = (inb && ing) ? ((b * NXX + xi) * NYY + yi) : -1;
    }
    __syncthreads();
    if (tid == 0) { __threadfence(); atomicAdd(&arg_done_g, 1u); }
}

extern "C" void kernel_launch(void* const* d_in, const int* in_sizes, int n_in,
                              void* d_out, int out_size) {
    const float* depth = (const float*)d_in[0];
    const float* feats = (const float*)d_in[1];
    const float* intr  = (const float*)d_in[2];
    const float* rot   = (const float*)d_in[3];
    float* out = (float*)d_out;

    mega_kernel<<<TOTAL_BLOCKS, 256>>>(depth, feats, intr, rot, out,
                                       (long long)out_size);
}

// round 13
// speedup vs baseline: 1.0324x; 1.0324x over previous
#include <cuda_runtime.h>

#define BB    8
#define DD    472
#define CC    472
#define FHH   56
#define FWW   100
#define NPIX  (FHH * FWW)      // 5600
#define NXX   160
#define NYY   160

#define SEGS       8
#define BINS_SEG   59                        // 8 * 59 = 472
#define ARG_BLOCKS  ((BB * NPIX) / 32)       // 1400
#define ZERO_BLOCKS 8072
#define SCAT_BLOCKS ((BB * NPIX) / 8)        // 5600 (warp per pixel, 8 warps/block)
#define TOTAL_BLOCKS (ARG_BLOCKS + ZERO_BLOCKS + SCAT_BLOCKS)
#define NCHUNK     (CC / 4)                  // 118 float4 chunks

// per-pixel BEV segment (or -1), rewritten fully every launch
__device__ int pix2seg_g[BB * NPIX];
// progress counters (zero at load; self-reset by last scatter block each launch)
__device__ unsigned arg_done_g;
__device__ unsigned zero_done_g;
__device__ unsigned scat_done_g;

__device__ __forceinline__ void inv3x3(const float a[9], float m[9]) {
    float A  =  (a[4] * a[8] - a[5] * a[7]);
    float Bc = -(a[3] * a[8] - a[5] * a[6]);
    float Cc =  (a[3] * a[7] - a[4] * a[6]);
    float Dv = -(a[1] * a[8] - a[2] * a[7]);
    float E  =  (a[0] * a[8] - a[2] * a[6]);
    float F  = -(a[0] * a[7] - a[1] * a[6]);
    float G  =  (a[1] * a[5] - a[2] * a[4]);
    float Hc = -(a[0] * a[5] - a[2] * a[3]);
    float I  =  (a[0] * a[4] - a[1] * a[3]);
    float det = a[0] * A + a[1] * Bc + a[2] * Cc;
    m[0] = A  / det;  m[1] = Dv / det;  m[2] = G  / det;
    m[3] = Bc / det;  m[4] = E  / det;  m[5] = Hc / det;
    m[6] = Cc / det;  m[7] = F  / det;  m[8] = I  / det;
}

__device__ __forceinline__ void red_add_v4(float* addr, float a, float b,
                                           float c, float d) {
    asm volatile("red.global.add.v4.f32 [%0], {%1, %2, %3, %4};"
                 :: "l"(addr), "f"(a), "f"(b), "f"(c), "f"(d) : "memory");
}

// cheap gate: volatile load poll (no atomic), exponential backoff
__device__ __forceinline__ void wait_counter(unsigned* ctr, unsigned target) {
    unsigned ns = 128;
    while (*((volatile unsigned*)ctr) < target) {
        __nanosleep(ns);
        if (ns < 4096) ns <<= 1;
    }
    __threadfence();   // acquire
}

__global__ void __launch_bounds__(256)
mega_kernel(const float* __restrict__ depth,   // [B, D, FH, FW]
            const float* __restrict__ feats,   // [B, C, FH, FW]
            const float* __restrict__ intr,    // [B, 3, 3]
            const float* __restrict__ rot,     // [B, 3, 3]
            float* __restrict__ out,           // [B, NX, NY, C]
            long long nout)
{
    int bx  = blockIdx.x;
    int tid = threadIdx.x;

    // ===================== role 2: zero-fill =====================
    if (bx >= ARG_BLOCKS && bx < ARG_BLOCKS + ZERO_BLOCKS) {
        long long n4 = nout >> 2;
        float4* o4 = reinterpret_cast<float4*>(out);
        long long i = (long long)(bx - ARG_BLOCKS) * 256 + tid;
        long long stride = (long long)ZERO_BLOCKS * 256;
        float4 z = make_float4(0.f, 0.f, 0.f, 0.f);
        for (; i < n4; i += stride) __stcs(&o4[i], z);
        __syncthreads();
        if (tid == 0) { __threadfence(); atomicAdd(&zero_done_g, 1u); }
        return;
    }

    // ===================== role 3: scatter =====================
    if (bx >= ARG_BLOCKS + ZERO_BLOCKS) {
        int sb   = bx - (ARG_BLOCKS + ZERO_BLOCKS);
        int lane = tid & 31;
        int wid  = tid >> 5;
        int pix  = sb * 8 + wid;                 // warp per pixel

        // gate1: pix2seg ready (arg blocks finished waves earlier)
        if (tid == 0) wait_counter(&arg_done_g, ARG_BLOCKS);
        __syncthreads();

        int seg = __ldg(&pix2seg_g[pix]);

        int b  = pix / NPIX;
        int hw = pix - b * NPIX;
        const float* fp = feats + (size_t)b * CC * NPIX + hw;

        float v[4][4];
        bool has4 = (lane < (NCHUNK - 96));      // lane < 22
        if (seg >= 0) {
            #pragma unroll
            for (int r = 0; r < 3; r++) {
                int c = (r * 32 + lane) * 4;
                #pragma unroll
                for (int k = 0; k < 4; k++)
                    v[r][k] = __ldg(&fp[(size_t)(c + k) * NPIX]);
            }
            if (has4) {
                int c = (96 + lane) * 4;
                #pragma unroll
                for (int k = 0; k < 4; k++)
                    v[3][k] = __ldg(&fp[(size_t)(c + k) * NPIX]);
            }
        }

        // gate2: output fully zeroed (cheap volatile poll + backoff)
        if (tid == 0) wait_counter(&zero_done_g, ZERO_BLOCKS);
        __syncthreads();

        if (seg >= 0) {
            float* op = out + (size_t)seg * CC;
            #pragma unroll
            for (int r = 0; r < 3; r++) {
                int c = (r * 32 + lane) * 4;
                red_add_v4(&op[c], v[r][0], v[r][1], v[r][2], v[r][3]);
            }
            if (has4) {
                int c = (96 + lane) * 4;
                red_add_v4(&op[c], v[3][0], v[3][1], v[3][2], v[3][3]);
            }
        }

        __syncthreads();
        if (tid == 0) {
            unsigned d = atomicAdd(&scat_done_g, 1u) + 1u;
            if (d == SCAT_BLOCKS) {       // last scatter block: reset for replay
                arg_done_g  = 0u;
                zero_done_g = 0u;
                scat_done_g = 0u;
                __threadfence();
            }
        }
        return;
    }

    // ===================== role 1: argmax + geometry =====================
    int tx = tid & 31;            // pixel within tile
    int ty = tid >> 5;            // depth segment
    int pix = bx * 32 + tx;
    int b  = pix / NPIX;
    int hw = pix - b * NPIX;

    const float* dp = depth + (size_t)b * DD * NPIX + hw;
    int base = ty * BINS_SEG;
    float best = dp[(size_t)base * NPIX];
    int   bi   = base;
    #pragma unroll
    for (int k = 1; k < BINS_SEG; k++) {
        float vv = dp[(size_t)(base + k) * NPIX];
        if (vv > best) { best = vv; bi = base + k; }
    }

    __shared__ float sval[SEGS][32];
    __shared__ int   sidx[SEGS][32];
    sval[ty][tx] = best;
    sidx[ty][tx] = bi;
    __syncthreads();

    if (ty == 0) {
        // reduce across depth segments in ascending order (first max wins)
        float bv = sval[0][tx];
        int  bix = sidx[0][tx];
        #pragma unroll
        for (int s = 1; s < SEGS; s++) {
            float vv = sval[s][tx];
            if (vv > bv) { bv = vv; bix = sidx[s][tx]; }
        }
        float d = (float)bix * 0.125f + 1.0f;

        // combine = R * inv(K), float32, ascending-j fma
        float a[9], invK[9], Cm[9];
        #pragma unroll
        for (int i = 0; i < 9; i++) a[i] = intr[b * 9 + i];
        inv3x3(a, invK);
        #pragma unroll
        for (int i = 0; i < 3; i++) {
            #pragma unroll
            for (int j = 0; j < 3; j++) {
                float acc = rot[b * 9 + i * 3 + 0] * invK[0 * 3 + j];
                acc = fmaf(rot[b * 9 + i * 3 + 1], invK[1 * 3 + j], acc);
                acc = fmaf(rot[b * 9 + i * 3 + 2], invK[2 * 3 + j], acc);
                Cm[i * 3 + j] = acc;
            }
        }

        int h = hw / FWW;
        int w = hw - h * FWW;
        const float DU = 1600.0f / 99.0f;
        const float DV = 896.0f / 55.0f;
        float u  = (float)w * DU;
        float v  = (float)h * DV;
        float ud = u * d;
        float vd = v * d;

        float x = fmaf(Cm[2], d, fmaf(Cm[1], vd, Cm[0] * ud));
        float y = fmaf(Cm[5], d, fmaf(Cm[4], vd, Cm[3] * ud));
        float z = fmaf(Cm[8], d, fmaf(Cm[7], vd, Cm[6] * ud));

        bool inb = (x > 1.0f) && (x < 41.0f) &&
                   (y > -20.0f) && (y < 20.0f) &&
                   (z > -10.0f) && (z < 10.0f);
        float fxv = floorf((x - 1.0f) * 4.0f);
        float fyv = floorf((y + 20.0f) * 4.0f);
        float fzv = floorf((z + 10.0f) / 20.0f);
        int xi = (int)fxv, yi = (int)fyv, zi = (int)fzv;
        bool ing = (xi >= 0) && (xi < NXX) && (yi >= 0) && (yi < NYY) &&
                   (zi >= 0) && (zi < 1);

        pix2seg_g[pix] = (inb && ing) ? ((b * NXX + xi) * NYY + yi) : -1;
    }
    __syncthreads();
    if (tid == 0) { __threadfence(); atomicAdd(&arg_done_g, 1u); }
}

extern "C" void kernel_launch(void* const* d_in, const int* in_sizes, int n_in,
                              void* d_out, int out_size) {
    const float* depth = (const float*)d_in[0];
    const float* feats = (const float*)d_in[1];
    const float* intr  = (const float*)d_in[2];
    const float* rot   = (const float*)d_in[3];
    float* out = (float*)d_out;

    mega_kernel<<<TOTAL_BLOCKS, 256>>>(depth, feats, intr, rot, out,
                                       (long long)out_size);
}

// round 14
// speedup vs baseline: 1.1643x; 1.1278x over previous
#include <cuda_runtime.h>

#define BB    8
#define DD    472
#define CC    472
#define FHH   56
#define FWW   100
#define NPIX  (FHH * FWW)      // 5600
#define NXX   160
#define NYY   160

#define SEGS       8
#define BINS_SEG   59                      // 8 * 59 = 472
#define ARG_BLOCKS ((BB * NPIX) / 32)      // 1400
#define ZERO_BLOCKS 8072                   // full waves with ARG
#define NCHUNK     (CC / 4)                // 118 float4 chunks
#define NGRP       (BB * NPIX / 8)         // 5600 groups of 8 pixels
#define SP         476                     // smem pitch (floats): conflict-free, 16B-aligned

// per-pixel BEV segment (or -1), rewritten fully every launch
__device__ int pix2seg_g[BB * NPIX];

__device__ __forceinline__ void inv3x3(const float a[9], float m[9]) {
    float A  =  (a[4] * a[8] - a[5] * a[7]);
    float Bc = -(a[3] * a[8] - a[5] * a[6]);
    float Cc =  (a[3] * a[7] - a[4] * a[6]);
    float Dv = -(a[1] * a[8] - a[2] * a[7]);
    float E  =  (a[0] * a[8] - a[2] * a[6]);
    float F  = -(a[0] * a[7] - a[1] * a[6]);
    float G  =  (a[1] * a[5] - a[2] * a[4]);
    float Hc = -(a[0] * a[5] - a[2] * a[3]);
    float I  =  (a[0] * a[4] - a[1] * a[3]);
    float det = a[0] * A + a[1] * Bc + a[2] * Cc;
    m[0] = A  / det;  m[1] = Dv / det;  m[2] = G  / det;
    m[3] = Bc / det;  m[4] = E  / det;  m[5] = Hc / det;
    m[6] = Cc / det;  m[7] = F  / det;  m[8] = I  / det;
}

__device__ __forceinline__ void red_add_v4(float* addr, float a, float b,
                                           float c, float d) {
    asm volatile("red.global.add.v4.f32 [%0], {%1, %2, %3, %4};"
                 :: "l"(addr), "f"(a), "f"(b), "f"(c), "f"(d) : "memory");
}

// Fused: blocks [0, ARG_BLOCKS) -> depth argmax + geometry -> pix2seg_g,
//        (PDL trigger after pix2seg write). Blocks [ARG_BLOCKS,...) -> zero.
__global__ void __launch_bounds__(256)
fused_kernel(const float* __restrict__ depth,   // [B, D, FH, FW]
             const float* __restrict__ intr,    // [B, 3, 3]
             const float* __restrict__ rot,     // [B, 3, 3]
             float* __restrict__ out,           // [B, NX, NY, C]
             long long nout)
{
    if (blockIdx.x >= ARG_BLOCKS) {
        cudaTriggerProgrammaticLaunchCompletion();
        long long n4 = nout >> 2;
        float4* o4 = reinterpret_cast<float4*>(out);
        long long i = (long long)(blockIdx.x - ARG_BLOCKS) * 256 + threadIdx.x;
        long long stride = (long long)ZERO_BLOCKS * 256;
        float4 z = make_float4(0.f, 0.f, 0.f, 0.f);
        for (; i < n4; i += stride) __stcs(&o4[i], z);
        return;
    }

    // ---- argmax: 32 pixels per block, 8 depth-segments (one warp each) ----
    int tx = threadIdx.x & 31;
    int ty = threadIdx.x >> 5;
    int pix = blockIdx.x * 32 + tx;
    int b  = pix / NPIX;
    int hw = pix - b * NPIX;

    const float* dp = depth + (size_t)b * DD * NPIX + hw;
    int base = ty * BINS_SEG;
    float best = dp[(size_t)base * NPIX];
    int   bi   = base;
    #pragma unroll
    for (int k = 1; k < BINS_SEG; k++) {
        float v = dp[(size_t)(base + k) * NPIX];
        if (v > best) { best = v; bi = base + k; }
    }

    __shared__ float sval[SEGS][32];
    __shared__ int   sidx[SEGS][32];
    sval[ty][tx] = best;
    sidx[ty][tx] = bi;
    __syncthreads();

    if (ty == 0) {
        float bv = sval[0][tx];
        int  bix = sidx[0][tx];
        #pragma unroll
        for (int s = 1; s < SEGS; s++) {
            float v = sval[s][tx];
            if (v > bv) { bv = v; bix = sidx[s][tx]; }
        }
        float d = (float)bix * 0.125f + 1.0f;

        float a[9], invK[9], Cm[9];
        #pragma unroll
        for (int i = 0; i < 9; i++) a[i] = intr[b * 9 + i];
        inv3x3(a, invK);
        #pragma unroll
        for (int i = 0; i < 3; i++) {
            #pragma unroll
            for (int j = 0; j < 3; j++) {
                float acc = rot[b * 9 + i * 3 + 0] * invK[0 * 3 + j];
                acc = fmaf(rot[b * 9 + i * 3 + 1], invK[1 * 3 + j], acc);
                acc = fmaf(rot[b * 9 + i * 3 + 2], invK[2 * 3 + j], acc);
                Cm[i * 3 + j] = acc;
            }
        }

        int h = hw / FWW;
        int w = hw - h * FWW;
        const float DU = 1600.0f / 99.0f;
        const float DV = 896.0f / 55.0f;
        float u  = (float)w * DU;
        float v  = (float)h * DV;
        float ud = u * d;
        float vd = v * d;

        float x = fmaf(Cm[2], d, fmaf(Cm[1], vd, Cm[0] * ud));
        float y = fmaf(Cm[5], d, fmaf(Cm[4], vd, Cm[3] * ud));
        float z = fmaf(Cm[8], d, fmaf(Cm[7], vd, Cm[6] * ud));

        bool inb = (x > 1.0f) && (x < 41.0f) &&
                   (y > -20.0f) && (y < 20.0f) &&
                   (z > -10.0f) && (z < 10.0f);
        float fxv = floorf((x - 1.0f) * 4.0f);
        float fyv = floorf((y + 20.0f) * 4.0f);
        float fzv = floorf((z + 10.0f) / 20.0f);
        int xi = (int)fxv, yi = (int)fyv, zi = (int)fzv;
        bool ing = (xi >= 0) && (xi < NXX) && (yi >= 0) && (yi < NYY) &&
                   (zi >= 0) && (zi < 1);

        pix2seg_g[pix] = (inb && ing) ? ((b * NXX + xi) * NYY + yi) : -1;
    }
    __syncthreads();
    __threadfence();
    cudaTriggerProgrammaticLaunchCompletion();
}

// Scatter: block = 8 consecutive pixels.
//  Phase A: coalesced loads — warp instr touches 4 sectors (4 ch x 8 px),
//           all useful; store to conflict-free smem (pitch 476).
//  Phase B: warp per pixel, contiguous float4 LDS -> red.v4 (512B runs).
__global__ void __launch_bounds__(256)
scatter_kernel(const float* __restrict__ feats,   // [B, C, FH, FW]
               float* __restrict__ out)           // [B*NX*NY, C]
{
    __shared__ float s[8 * SP];
    __shared__ int   segs[8];

    int tid  = threadIdx.x;
    int lane = tid & 31;
    int wid  = tid >> 5;
    int grp  = blockIdx.x;
    int pix0 = grp * 8;                    // NPIX % 8 == 0: no batch straddle
    int b    = pix0 / NPIX;
    int hw0  = pix0 - b * NPIX;

    int myseg = -1;
    if (tid < 8) {
        myseg = __ldg(&pix2seg_g[pix0 + tid]);
        segs[tid] = myseg;
    }
    // group-skip: warp 0 knows all 8 segs
    if (__ballot_sync(0xffffffffu, myseg >= 0) == 0 && wid == 0) {
        // fallthrough handled below via shared flag
    }
    __syncthreads();

    bool any = false;
    #pragma unroll
    for (int p = 0; p < 8; p++) any |= (segs[p] >= 0);
    if (!any) return;

    // ---- Phase A: coalesced gather into smem ----
    int p    = tid & 7;                    // pixel within group
    int crow = tid >> 3;                   // 0..31 channel row
    const float* fp = feats + (size_t)b * CC * NPIX + hw0 + p;
    #pragma unroll
    for (int i = 0; i < 15; i++) {
        int c = i * 32 + crow;
        if (c < CC)
            s[p * SP + c] = __ldg(&fp[(size_t)c * NPIX]);
    }
    __syncthreads();

    // zero-fill must be complete before REDs
    cudaGridDependencySynchronize();

    // ---- Phase B: warp per pixel, red.v4 from smem ----
    if (wid < 8) {
        int seg = segs[wid];
        if (seg >= 0) {
            const float4* sp = reinterpret_cast<const float4*>(&s[wid * SP]);
            float* op = out + (size_t)seg * CC;
            #pragma unroll
            for (int r = 0; r < 3; r++) {
                float4 v = sp[r * 32 + lane];
                red_add_v4(&op[(r * 32 + lane) * 4], v.x, v.y, v.z, v.w);
            }
            if (lane < NCHUNK - 96) {
                float4 v = sp[96 + lane];
                red_add_v4(&op[(96 + lane) * 4], v.x, v.y, v.z, v.w);
            }
        }
    }
}

extern "C" void kernel_launch(void* const* d_in, const int* in_sizes, int n_in,
                              void* d_out, int out_size) {
    const float* depth = (const float*)d_in[0];
    const float* feats = (const float*)d_in[1];
    const float* intr  = (const float*)d_in[2];
    const float* rot   = (const float*)d_in[3];
    float* out = (float*)d_out;

    fused_kernel<<<ARG_BLOCKS + ZERO_BLOCKS, 256>>>(depth, intr, rot, out,
                                                    (long long)out_size);

    cudaLaunchConfig_t cfg = {};
    cfg.gridDim  = dim3(NGRP, 1, 1);       // 5600 blocks
    cfg.blockDim = dim3(256, 1, 1);
    cfg.dynamicSmemBytes = 0;
    cfg.stream = 0;
    cudaLaunchAttribute attrs[1];
    attrs[0].id = cudaLaunchAttributeProgrammaticStreamSerialization;
    attrs[0].val.programmaticStreamSerializationAllowed = 1;
    cfg.attrs = attrs;
    cfg.numAttrs = 1;
    cudaLaunchKernelEx(&cfg, scatter_kernel, feats, out);
}